// round 8
// baseline (speedup 1.0000x reference)
#include <cuda_runtime.h>
#include <math.h>
#include <cstdint>
#include <cstddef>

#define NN    50000
#define NE    800000
#define NG    256
#define D_IN  128
#define D_HID 64
#define D_OUT 128

typedef unsigned long long ull;

// ---------------- device scratch (no allocations allowed) ----------------
__device__ int   g_deg[NN];
__device__ int   g_fill[NN];
__device__ int   g_rowptr[NN + 1];
__device__ float g_dinv[NN];
__device__ int   g_src[NE];
__device__ int   g_dst[NE];
__device__ __align__(16) int2 g_edge[NE];   // (src, norm-as-int) packed
__device__ __align__(16) float g_bufA[(size_t)NN * D_HID];
__device__ __align__(16) float g_bufB[(size_t)NN * D_HID];
__device__ float g_psum[NG * D_HID];
__device__ int   g_pcnt[NG];
__device__ int   g_idx64;   // 1 if edge_index/batch are int64, 0 if int32

// ---------------- f32x2 packed-math helpers ----------------
__device__ __forceinline__ void ffma2(ull& d, ull a, ull b) {
  asm("fma.rn.f32x2 %0, %1, %2, %0;" : "+l"(d) : "l"(a), "l"(b));
}
__device__ __forceinline__ ull fmul2(ull a, ull b) {
  ull d; asm("mul.rn.f32x2 %0, %1, %2;" : "=l"(d) : "l"(a), "l"(b)); return d;
}
__device__ __forceinline__ ull pack2(float lo, float hi) {
  ull d; asm("mov.b64 %0, {%1, %2};" : "=l"(d) : "f"(lo), "f"(hi)); return d;
}
__device__ __forceinline__ float2 unpack2(ull v) {
  float2 r; asm("mov.b64 {%0, %1}, %2;" : "=f"(r.x), "=f"(r.y) : "l"(v)); return r;
}

// gelu(tanh approx) == x * sigmoid(1.5957691*(x + 0.044715 x^3))
__device__ __forceinline__ float gelu_fast(float x) {
  float s = x + 0.044715f * x * x * x;
  return __fdividef(x, 1.0f + __expf(-1.59576912f * s));
}

__device__ __forceinline__ int load_idx(const void* p, long long i) {
  if (g_idx64) return (int)((const long long*)p)[i];
  return ((const int*)p)[i];
}

// ---------------- init + dtype detect (fused) ----------------
__global__ void init_kernel(const void* __restrict__ ei, int n_nodes, int N) {
  int i = blockIdx.x * blockDim.x + threadIdx.x;
  if (i == 0) {
    const long long* p = (const long long*)ei;
    int ok = 1;
    for (int k = 0; k < 64; k++) {
      long long v = p[k];
      if (v < 0 || v >= (long long)N) { ok = 0; break; }
    }
    g_idx64 = ok;
  }
  if (i < n_nodes) { g_deg[i] = 0; g_fill[i] = 0; }
  if (i < NG * D_HID) g_psum[i] = 0.0f;
  if (i < NG) g_pcnt[i] = 0;
}

__global__ void hist_kernel(const void* __restrict__ ei, int E) {
  int e = blockIdx.x * blockDim.x + threadIdx.x;
  if (e >= E) return;
  int s = load_idx(ei, e);
  int d = load_idx(ei, (long long)E + e);
  g_src[e] = s;
  g_dst[e] = d;
  atomicAdd(&g_deg[d], 1);
}

// single-block exclusive scan of g_deg -> g_rowptr, fused dinv
__global__ void scan_kernel(int n) {
  __shared__ int sums[1024];
  int tid   = threadIdx.x;
  int chunk = (n + 1023) >> 10;
  int start = tid * chunk;
  int end   = min(start + chunk, n);
  int s = 0;
  for (int i = start; i < end; i++) s += g_deg[i];
  sums[tid] = s;
  __syncthreads();
  for (int off = 1; off < 1024; off <<= 1) {
    int v = 0;
    if (tid >= off) v = sums[tid - off];
    __syncthreads();
    sums[tid] += v;
    __syncthreads();
  }
  int run = (tid == 0) ? 0 : sums[tid - 1];
  for (int i = start; i < end; i++) {
    int d = g_deg[i];
    g_rowptr[i] = run;
    g_dinv[i]   = rsqrtf((float)d + 1.0f);   // self-loop: deg+1
    run += d;
  }
  if (end == n) g_rowptr[n] = run;
}

__global__ void scatter_kernel(int E) {
  int e = blockIdx.x * blockDim.x + threadIdx.x;
  if (e >= E) return;
  int s = g_src[e];
  int d = g_dst[e];
  int pos = g_rowptr[d] + atomicAdd(&g_fill[d], 1);
  g_edge[pos] = make_int2(s, __float_as_int(g_dinv[s] * g_dinv[d]));
}

// ---------------- dense GEMM: H[M,64] = X[M,K] @ W[K,64], f32x2 ------------
// BM=128, KB=32, 256 threads. Per-thread 8 rows (4 packed pairs) x 4 cols.
// X transposed in smem (row pairs adjacent -> b64 loads); W duplicated in
// smem (float2 load == (w,w) operand). Inner loop = pure FFMA2 + LDS.b64.
template <int K>
__global__ void gemm_kernel(const float* __restrict__ X,
                            const float* __restrict__ W,
                            float* __restrict__ H, int M) {
  constexpr int NOUT = D_HID;
  constexpr int BM = 128;
  constexpr int KB = 32;
  constexpr int XS = BM + 4;                    // 132: rows stay 16B-aligned
  __shared__ __align__(16) float Xs[KB][XS];    // transposed: Xs[k][r]
  __shared__ __align__(16) float Wd[KB][2 * NOUT];

  int tid = threadIdx.x;
  int tx  = tid & 15;
  int ty  = tid >> 4;
  int rb  = blockIdx.x * BM;

  ull acc[4][4];
#pragma unroll
  for (int p = 0; p < 4; p++)
#pragma unroll
    for (int j = 0; j < 4; j++) acc[p][j] = 0ull;

  for (int k0 = 0; k0 < K; k0 += KB) {
#pragma unroll
    for (int i = tid; i < BM * KB; i += 256) {
      int r = i >> 5, k = i & 31;
      int gr = rb + r;
      Xs[k][r] = (gr < M) ? X[(size_t)gr * K + k0 + k] : 0.0f;
    }
#pragma unroll
    for (int i = tid; i < KB * NOUT; i += 256) {
      int k = i >> 6, c = i & 63;
      float v = W[(size_t)(k0 + k) * NOUT + c];
      Wd[k][2 * c]     = v;
      Wd[k][2 * c + 1] = v;
    }
    __syncthreads();
#pragma unroll
    for (int k = 0; k < KB; k++) {
      const ull* xp = reinterpret_cast<const ull*>(&Xs[k][ty * 8]);
      const ull* wp = reinterpret_cast<const ull*>(&Wd[k][tx * 8]);
      ull xr[4] = {xp[0], xp[1], xp[2], xp[3]};
      ull wr[4] = {wp[0], wp[1], wp[2], wp[3]};
#pragma unroll
      for (int p = 0; p < 4; p++)
#pragma unroll
        for (int j = 0; j < 4; j++) ffma2(acc[p][j], xr[p], wr[j]);
    }
    __syncthreads();
  }

#pragma unroll
  for (int p = 0; p < 4; p++) {
    int r0 = rb + ty * 8 + 2 * p;
    float2 c0 = unpack2(acc[p][0]);
    float2 c1 = unpack2(acc[p][1]);
    float2 c2 = unpack2(acc[p][2]);
    float2 c3 = unpack2(acc[p][3]);
    if (r0 < M)
      *reinterpret_cast<float4*>(H + (size_t)r0 * NOUT + tx * 4) =
          make_float4(c0.x, c1.x, c2.x, c3.x);
    if (r0 + 1 < M)
      *reinterpret_cast<float4*>(H + (size_t)(r0 + 1) * NOUT + tx * 4) =
          make_float4(c0.y, c1.y, c2.y, c3.y);
  }
}

// ------- CSR aggregation core (F=64, warp per node, f32x2) ------------------
__device__ __forceinline__ ull agg_node(const float* __restrict__ H,
                                        int n, int lane) {
  float dn = g_dinv[n];
  ull acc = __ldg(reinterpret_cast<const ull*>(H + (size_t)n * D_HID) + lane);
  acc = fmul2(acc, pack2(dn * dn, dn * dn));

  int e  = g_rowptr[n];
  int e1 = g_rowptr[n + 1];
  for (; e + 1 < e1; e += 2) {
    int2 v0 = __ldg(&g_edge[e]);
    int2 v1 = __ldg(&g_edge[e + 1]);
    ull h0 = __ldg(reinterpret_cast<const ull*>(H + (size_t)v0.x * D_HID) + lane);
    ull h1 = __ldg(reinterpret_cast<const ull*>(H + (size_t)v1.x * D_HID) + lane);
    float w0 = __int_as_float(v0.y);
    float w1 = __int_as_float(v1.y);
    ffma2(acc, h0, pack2(w0, w0));
    ffma2(acc, h1, pack2(w1, w1));
  }
  if (e < e1) {
    int2 v = __ldg(&g_edge[e]);
    ull h = __ldg(reinterpret_cast<const ull*>(H + (size_t)v.x * D_HID) + lane);
    float w = __int_as_float(v.y);
    ffma2(acc, h, pack2(w, w));
  }
  return acc;
}

__global__ void agg_gelu_kernel(const float* __restrict__ H,
                                const float* __restrict__ bias,
                                float* __restrict__ out, int N) {
  int t = blockIdx.x * blockDim.x + threadIdx.x;
  int n = t >> 5, lane = t & 31;
  if (n >= N) return;
  float2 a = unpack2(agg_node(H, n, lane));
  float2 b = __ldg(reinterpret_cast<const float2*>(bias) + lane);
  float y0 = gelu_fast(a.x + b.x);
  float y1 = gelu_fast(a.y + b.y);
  reinterpret_cast<float2*>(out + (size_t)n * D_HID)[lane] = make_float2(y0, y1);
}

// ------- layer-3 agg fused with mean-pool; batch is sorted so a block's 8
// nodes almost always share one graph -> smem-reduce, one flush per block. ---
__global__ void agg_pool_kernel(const float* __restrict__ H,
                                const void* __restrict__ batch, int N) {
  __shared__ float sacc[D_HID];
  __shared__ int   scnt;
  __shared__ int   sg;
  int tid  = threadIdx.x;
  int lane = tid & 31, wid = tid >> 5;
  int n = blockIdx.x * 8 + wid;

  if (tid == 0) {
    scnt = 0;
    int first = blockIdx.x * 8;
    sg = load_idx(batch, first < N ? first : (N - 1));
  }
  if (tid < D_HID) sacc[tid] = 0.0f;
  __syncthreads();

  if (n < N) {
    float2 a = unpack2(agg_node(H, n, lane));
    int g = load_idx(batch, n);
    if (g == sg) {
      atomicAdd(&sacc[lane * 2],     a.x);
      atomicAdd(&sacc[lane * 2 + 1], a.y);
      if (lane == 0) atomicAdd(&scnt, 1);
    } else {
      atomicAdd(&g_psum[g * D_HID + lane * 2],     a.x);
      atomicAdd(&g_psum[g * D_HID + lane * 2 + 1], a.y);
      if (lane == 0) atomicAdd(&g_pcnt[g], 1);
    }
  }
  __syncthreads();
  if (scnt > 0) {
    if (tid < D_HID) atomicAdd(&g_psum[sg * D_HID + tid], sacc[tid]);
    if (tid == 0)    atomicAdd(&g_pcnt[sg], scnt);
  }
}

// ------- final tiny GEMM: out[g,:] = mean_g @ W3 + b3 -----------------------
__global__ void final_gemm_kernel(const float* __restrict__ W3,
                                  const float* __restrict__ b3,
                                  float* __restrict__ out) {
  int g = blockIdx.x;
  int j = threadIdx.x;  // 128 threads = D_OUT
  __shared__ float row[D_HID];
  int cnt = g_pcnt[g];
  float inv = (cnt > 0) ? (1.0f / (float)cnt) : 0.0f;
  if (j < D_HID) row[j] = g_psum[g * D_HID + j] * inv;
  __syncthreads();
  float acc = (cnt > 0) ? __ldg(&b3[j]) : 0.0f;
#pragma unroll 8
  for (int k = 0; k < D_HID; k++) acc += row[k] * __ldg(&W3[k * D_OUT + j]);
  out[(size_t)g * D_OUT + j] = acc;
}

// ---------------- launch ----------------
extern "C" void kernel_launch(void* const* d_in, const int* in_sizes, int n_in,
                              void* d_out, int out_size) {
  const float* x     = (const float*)d_in[0];
  const void*  ei    = d_in[1];
  const void*  batch = d_in[2];

  int wi = 3;
  while (wi < n_in && in_sizes[wi] <= 1) wi++;
  const float* W1 = (const float*)d_in[wi + 0];
  const float* b1 = (const float*)d_in[wi + 1];
  const float* W2 = (const float*)d_in[wi + 2];
  const float* b2 = (const float*)d_in[wi + 3];
  const float* W3 = (const float*)d_in[wi + 4];
  const float* b3 = (const float*)d_in[wi + 5];

  int N = in_sizes[2];
  int E = in_sizes[1] / 2;

  float *bufA, *bufB;
  cudaGetSymbolAddress((void**)&bufA, g_bufA);
  cudaGetSymbolAddress((void**)&bufB, g_bufB);

  const int TB = 256;
  int nb_nodes = (N + TB - 1) / TB;
  int nb_edges = (E + TB - 1) / TB;
  int nb_warp  = (int)(((long long)N * 32 + TB - 1) / TB);
  int nb_gemm  = (N + 127) / 128;

  // ---- preprocessing: CSR + symmetric norm ----
  init_kernel<<<nb_nodes, TB>>>(ei, N, N);
  hist_kernel<<<nb_edges, TB>>>(ei, E);
  scan_kernel<<<1, 1024>>>(N);
  scatter_kernel<<<nb_edges, TB>>>(E);

  // ---- layer 1: GEMM 128->64, agg + gelu ----
  gemm_kernel<D_IN><<<nb_gemm, TB>>>(x, W1, bufA, N);
  agg_gelu_kernel<<<nb_warp, TB>>>(bufA, b1, bufB, N);

  // ---- layer 2: GEMM 64->64, agg + gelu ----
  gemm_kernel<D_HID><<<nb_gemm, TB>>>(bufB, W2, bufA, N);
  agg_gelu_kernel<<<nb_warp, TB>>>(bufA, b2, bufB, N);

  // ---- layer 3 (reordered): agg+pool in 64-dim, then [NG,64]@[64,128]+b3 ----
  agg_pool_kernel<<<(N + 7) / 8, TB>>>(bufB, batch, N);
  final_gemm_kernel<<<out_size / D_OUT, D_OUT>>>(W3, b3, (float*)d_out);
}

// round 9
// speedup vs baseline: 1.2406x; 1.2406x over previous
#include <cuda_runtime.h>
#include <cuda_fp16.h>
#include <math.h>
#include <cstdint>
#include <cstddef>

#define NN    50000
#define NE    800000
#define NG    256
#define D_IN  128
#define D_HID 64
#define D_OUT 128

// ---------------- device scratch (no allocations allowed) ----------------
__device__ int   g_deg[NN];
__device__ int   g_fill[NN];
__device__ int   g_rowptr[NN + 1];
__device__ float g_dinv[NN];
__device__ int   g_src[NE];
__device__ int   g_dst[NE];
__device__ __align__(16) int2 g_edge[NE];   // (src, norm-as-int) packed
__device__ __align__(16) __half g_bufA[(size_t)NN * D_HID];
__device__ __align__(16) __half g_bufB[(size_t)NN * D_HID];
__device__ float g_psum[NG * D_HID];
__device__ int   g_pcnt[NG];
__device__ int   g_idx64;   // 1 if edge_index/batch are int64, 0 if int32

// ---------------- helpers ----------------
// gelu(tanh approx) == x * sigmoid(1.5957691*(x + 0.044715 x^3))
__device__ __forceinline__ float gelu_fast(float x) {
  float s = x + 0.044715f * x * x * x;
  return __fdividef(x, 1.0f + __expf(-1.59576912f * s));
}

__device__ __forceinline__ int load_idx(const void* p, long long i) {
  if (g_idx64) return (int)((const long long*)p)[i];
  return ((const int*)p)[i];
}

__device__ __forceinline__ float load_x(const float* X, size_t i) { return X[i]; }
__device__ __forceinline__ float load_x(const __half* X, size_t i) {
  return __half2float(X[i]);
}

// ---------------- init + dtype detect (fused) ----------------
__global__ void init_kernel(const void* __restrict__ ei, int n_nodes, int N) {
  int i = blockIdx.x * blockDim.x + threadIdx.x;
  if (i == 0) {
    const long long* p = (const long long*)ei;
    int ok = 1;
    for (int k = 0; k < 64; k++) {
      long long v = p[k];
      if (v < 0 || v >= (long long)N) { ok = 0; break; }
    }
    g_idx64 = ok;
  }
  if (i < n_nodes) { g_deg[i] = 0; g_fill[i] = 0; }
  if (i < NG * D_HID) g_psum[i] = 0.0f;
  if (i < NG) g_pcnt[i] = 0;
}

// single-block exclusive scan of g_deg -> g_rowptr, fused dinv
__global__ void scan_kernel(int n) {
  __shared__ int sums[1024];
  int tid   = threadIdx.x;
  int chunk = (n + 1023) >> 10;
  int start = tid * chunk;
  int end   = min(start + chunk, n);
  int s = 0;
  for (int i = start; i < end; i++) s += g_deg[i];
  sums[tid] = s;
  __syncthreads();
  for (int off = 1; off < 1024; off <<= 1) {
    int v = 0;
    if (tid >= off) v = sums[tid - off];
    __syncthreads();
    sums[tid] += v;
    __syncthreads();
  }
  int run = (tid == 0) ? 0 : sums[tid - 1];
  for (int i = start; i < end; i++) {
    int d = g_deg[i];
    g_rowptr[i] = run;
    g_dinv[i]   = rsqrtf((float)d + 1.0f);   // self-loop: deg+1
    run += d;
  }
  if (end == n) g_rowptr[n] = run;
}

// ---------------- GEMM device body: H[M,64] = X[M,K] @ W[K,64] -------------
// R6-proven scalar core: BM=128, KB=32, 256 threads, 8x4 register tile.
// Output stored as fp16.
template <int K, typename T>
__device__ __forceinline__ void gemm_body(const T* __restrict__ X,
                                          const float* __restrict__ W,
                                          __half* __restrict__ H, int M,
                                          int gemmBid, int rowOffset) {
  constexpr int NOUT = D_HID;
  constexpr int BM = 128;
  constexpr int KB = 32;
  constexpr int XS = BM + 4;
  __shared__ __align__(16) float Xs[KB][XS];   // transposed: Xs[k][r]
  __shared__ __align__(16) float Ws[KB][NOUT];

  int tid = threadIdx.x;
  int tx  = tid & 15;
  int ty  = tid >> 4;
  int rb  = rowOffset + gemmBid * BM;

  float acc[8][4];
#pragma unroll
  for (int i = 0; i < 8; i++)
#pragma unroll
    for (int j = 0; j < 4; j++) acc[i][j] = 0.0f;

  for (int k0 = 0; k0 < K; k0 += KB) {
#pragma unroll
    for (int i = tid; i < BM * KB; i += 256) {
      int r = i >> 5, k = i & 31;
      int gr = rb + r;
      Xs[k][r] = (gr < M) ? load_x(X, (size_t)gr * K + k0 + k) : 0.0f;
    }
#pragma unroll
    for (int i = tid; i < KB * NOUT; i += 256) {
      int k = i >> 6, c = i & 63;
      Ws[k][c] = W[(size_t)(k0 + k) * NOUT + c];
    }
    __syncthreads();
#pragma unroll
    for (int k = 0; k < KB; k++) {
      float4 x0 = *reinterpret_cast<const float4*>(&Xs[k][ty * 8]);
      float4 x1 = *reinterpret_cast<const float4*>(&Xs[k][ty * 8 + 4]);
      float4 w  = *reinterpret_cast<const float4*>(&Ws[k][tx * 4]);
      float xr[8] = {x0.x, x0.y, x0.z, x0.w, x1.x, x1.y, x1.z, x1.w};
      float wr[4] = {w.x, w.y, w.z, w.w};
#pragma unroll
      for (int i = 0; i < 8; i++)
#pragma unroll
        for (int j = 0; j < 4; j++) acc[i][j] += xr[i] * wr[j];
    }
    __syncthreads();
  }

#pragma unroll
  for (int i = 0; i < 8; i++) {
    int gr = rb + ty * 8 + i;
    if (gr >= M) continue;
    __half2 h01 = __floats2half2_rn(acc[i][0], acc[i][1]);
    __half2 h23 = __floats2half2_rn(acc[i][2], acc[i][3]);
    uint2 u = make_uint2(*reinterpret_cast<unsigned*>(&h01),
                         *reinterpret_cast<unsigned*>(&h23));
    *reinterpret_cast<uint2*>(H + (size_t)gr * NOUT + tx * 4) = u;
  }
}

// ---- fused kernel A: GEMM1 (first half) blocks + histogram blocks ---------
template <int K, typename T>
__global__ void fused_hist_gemm(const void* __restrict__ ei, int E,
                                const T* __restrict__ X,
                                const float* __restrict__ W,
                                __half* __restrict__ H, int M,
                                int gemmBlocks, int rowOffset) {
  if ((int)blockIdx.x < gemmBlocks) {
    gemm_body<K>(X, W, H, M, blockIdx.x, rowOffset);
    return;
  }
  int e = (blockIdx.x - gemmBlocks) * blockDim.x + threadIdx.x;
  if (e >= E) return;
  int s = load_idx(ei, e);
  int d = load_idx(ei, (long long)E + e);
  g_src[e] = s;
  g_dst[e] = d;
  atomicAdd(&g_deg[d], 1);
}

// ---- fused kernel B: GEMM1 (second half) blocks + CSR-scatter blocks ------
template <int K, typename T>
__global__ void fused_scatter_gemm(int E,
                                   const T* __restrict__ X,
                                   const float* __restrict__ W,
                                   __half* __restrict__ H, int M,
                                   int gemmBlocks, int rowOffset) {
  if ((int)blockIdx.x < gemmBlocks) {
    gemm_body<K>(X, W, H, M, blockIdx.x, rowOffset);
    return;
  }
  int e = (blockIdx.x - gemmBlocks) * blockDim.x + threadIdx.x;
  if (e >= E) return;
  int s = g_src[e];
  int d = g_dst[e];
  int pos = g_rowptr[d] + atomicAdd(&g_fill[d], 1);
  g_edge[pos] = make_int2(s, __float_as_int(g_dinv[s] * g_dinv[d]));
}

// ---- plain GEMM (layer 2) --------------------------------------------------
template <int K, typename T>
__global__ void gemm_kernel(const T* __restrict__ X,
                            const float* __restrict__ W,
                            __half* __restrict__ H, int M) {
  gemm_body<K>(X, W, H, M, blockIdx.x, 0);
}

// ------- CSR aggregation core (F=64, warp per node, fp16 gather) -----------
__device__ __forceinline__ float2 agg_node(const __half* __restrict__ H,
                                           int n, int lane) {
  float dn = g_dinv[n];
  float ws = dn * dn;
  float2 self = __half22float2(
      __ldg(reinterpret_cast<const __half2*>(H + (size_t)n * D_HID) + lane));
  float a0 = self.x * ws, a1 = self.y * ws;

  int e  = g_rowptr[n];
  int e1 = g_rowptr[n + 1];
  for (; e + 1 < e1; e += 2) {
    int2 v0 = __ldg(&g_edge[e]);
    int2 v1 = __ldg(&g_edge[e + 1]);
    float2 h0 = __half22float2(
        __ldg(reinterpret_cast<const __half2*>(H + (size_t)v0.x * D_HID) + lane));
    float2 h1 = __half22float2(
        __ldg(reinterpret_cast<const __half2*>(H + (size_t)v1.x * D_HID) + lane));
    float w0 = __int_as_float(v0.y);
    float w1 = __int_as_float(v1.y);
    a0 += w0 * h0.x; a1 += w0 * h0.y;
    a0 += w1 * h1.x; a1 += w1 * h1.y;
  }
  if (e < e1) {
    int2 v = __ldg(&g_edge[e]);
    float2 h = __half22float2(
        __ldg(reinterpret_cast<const __half2*>(H + (size_t)v.x * D_HID) + lane));
    float w = __int_as_float(v.y);
    a0 += w * h.x; a1 += w * h.y;
  }
  return make_float2(a0, a1);
}

__global__ void agg_gelu_kernel(const __half* __restrict__ H,
                                const float* __restrict__ bias,
                                __half* __restrict__ out, int N) {
  int t = blockIdx.x * blockDim.x + threadIdx.x;
  int n = t >> 5, lane = t & 31;
  if (n >= N) return;
  float2 a = agg_node(H, n, lane);
  float2 b = __ldg(reinterpret_cast<const float2*>(bias) + lane);
  float y0 = gelu_fast(a.x + b.x);
  float y1 = gelu_fast(a.y + b.y);
  reinterpret_cast<__half2*>(out + (size_t)n * D_HID)[lane] =
      __floats2half2_rn(y0, y1);
}

// ------- layer-3 agg fused with mean-pool; batch sorted -> smem reduce -----
__global__ void agg_pool_kernel(const __half* __restrict__ H,
                                const void* __restrict__ batch, int N) {
  __shared__ float sacc[D_HID];
  __shared__ int   scnt;
  __shared__ int   sg;
  int tid  = threadIdx.x;
  int lane = tid & 31, wid = tid >> 5;
  int n = blockIdx.x * 8 + wid;

  if (tid == 0) {
    scnt = 0;
    int first = blockIdx.x * 8;
    sg = load_idx(batch, first < N ? first : (N - 1));
  }
  if (tid < D_HID) sacc[tid] = 0.0f;
  __syncthreads();

  if (n < N) {
    float2 a = agg_node(H, n, lane);
    int g = load_idx(batch, n);
    if (g == sg) {
      atomicAdd(&sacc[lane * 2],     a.x);
      atomicAdd(&sacc[lane * 2 + 1], a.y);
      if (lane == 0) atomicAdd(&scnt, 1);
    } else {
      atomicAdd(&g_psum[g * D_HID + lane * 2],     a.x);
      atomicAdd(&g_psum[g * D_HID + lane * 2 + 1], a.y);
      if (lane == 0) atomicAdd(&g_pcnt[g], 1);
    }
  }
  __syncthreads();
  if (scnt > 0) {
    if (tid < D_HID) atomicAdd(&g_psum[sg * D_HID + tid], sacc[tid]);
    if (tid == 0)    atomicAdd(&g_pcnt[sg], scnt);
  }
}

// ------- final tiny GEMM: out[g,:] = mean_g @ W3 + b3 -----------------------
__global__ void final_gemm_kernel(const float* __restrict__ W3,
                                  const float* __restrict__ b3,
                                  float* __restrict__ out) {
  int g = blockIdx.x;
  int j = threadIdx.x;  // 128 threads = D_OUT
  __shared__ float row[D_HID];
  int cnt = g_pcnt[g];
  float inv = (cnt > 0) ? (1.0f / (float)cnt) : 0.0f;
  if (j < D_HID) row[j] = g_psum[g * D_HID + j] * inv;
  __syncthreads();
  float acc = (cnt > 0) ? __ldg(&b3[j]) : 0.0f;
#pragma unroll 8
  for (int k = 0; k < D_HID; k++) acc += row[k] * __ldg(&W3[k * D_OUT + j]);
  out[(size_t)g * D_OUT + j] = acc;
}

// ---------------- launch ----------------
extern "C" void kernel_launch(void* const* d_in, const int* in_sizes, int n_in,
                              void* d_out, int out_size) {
  const float* x     = (const float*)d_in[0];
  const void*  ei    = d_in[1];
  const void*  batch = d_in[2];

  int wi = 3;
  while (wi < n_in && in_sizes[wi] <= 1) wi++;
  const float* W1 = (const float*)d_in[wi + 0];
  const float* b1 = (const float*)d_in[wi + 1];
  const float* W2 = (const float*)d_in[wi + 2];
  const float* b2 = (const float*)d_in[wi + 3];
  const float* W3 = (const float*)d_in[wi + 4];
  const float* b3 = (const float*)d_in[wi + 5];

  int N = in_sizes[2];
  int E = in_sizes[1] / 2;

  __half *bufA, *bufB;
  cudaGetSymbolAddress((void**)&bufA, g_bufA);
  cudaGetSymbolAddress((void**)&bufB, g_bufB);

  const int TB = 256;
  int nb_nodes = (N + TB - 1) / TB;
  int nb_edges = (E + TB - 1) / TB;
  int nb_warp  = (int)(((long long)N * 32 + TB - 1) / TB);
  int nb_gemm  = (N + 127) / 128;

  // Split GEMM1 blocks across the two preprocessing phases (50/50).
  int gA = nb_gemm / 2;
  int gB = nb_gemm - gA;
  int rowOffB = gA * 128;

  // ---- phase 0: init + dtype detect ----
  init_kernel<<<nb_nodes, TB>>>(ei, N, N);
  // ---- phase 1: GEMM1(first half) || histogram ----
  fused_hist_gemm<D_IN><<<gA + nb_edges, TB>>>(ei, E, x, W1, bufA, N, gA, 0);
  // ---- phase 2: rowptr scan + dinv ----
  scan_kernel<<<1, 1024>>>(N);
  // ---- phase 3: GEMM1(second half) || CSR scatter ----
  fused_scatter_gemm<D_IN><<<gB + nb_edges, TB>>>(E, x, W1, bufA, N, gB, rowOffB);

  // ---- layer 1 aggregation + gelu ----
  agg_gelu_kernel<<<nb_warp, TB>>>(bufA, b1, bufB, N);

  // ---- layer 2: GEMM 64->64, agg + gelu ----
  gemm_kernel<D_HID><<<nb_gemm, TB>>>(bufB, W2, bufA, N);
  agg_gelu_kernel<<<nb_warp, TB>>>(bufA, b2, bufB, N);

  // ---- layer 3 (reordered): agg+pool in 64-dim, then [NG,64]@[64,128]+b3 ----
  agg_pool_kernel<<<(N + 7) / 8, TB>>>(bufB, batch, N);
  final_gemm_kernel<<<out_size / D_OUT, D_OUT>>>(W3, b3, (float*)d_out);
}

// round 10
// speedup vs baseline: 1.3158x; 1.0605x over previous
#include <cuda_runtime.h>
#include <cuda_fp16.h>
#include <math.h>
#include <cstdint>
#include <cstddef>

#define NN    50000
#define NE    800000
#define NG    256
#define D_IN  128
#define D_HID 64
#define D_OUT 128

// ---------------- device scratch (no allocations allowed) ----------------
__device__ int   g_deg[NN];
__device__ int   g_fill[NN];
__device__ int   g_rowptr[NN + 1];
__device__ float g_dinv[NN];
__device__ int   g_src[NE];
__device__ int   g_dst[NE];
__device__ __align__(16) int2 g_edge[NE];   // (src, norm-as-int) packed
__device__ __align__(16) __half g_bufA[(size_t)NN * D_HID];
__device__ __align__(16) __half g_bufB[(size_t)NN * D_HID];
__device__ float g_psum[NG * D_HID];
__device__ int   g_pcnt[NG];
__device__ int   g_idx64;   // 1 if edge_index/batch are int64, 0 if int32

// ---------------- helpers ----------------
// gelu(tanh approx) == x * sigmoid(1.5957691*(x + 0.044715 x^3))
__device__ __forceinline__ float gelu_fast(float x) {
  float s = x + 0.044715f * x * x * x;
  return __fdividef(x, 1.0f + __expf(-1.59576912f * s));
}

__device__ __forceinline__ int load_idx(const void* p, long long i) {
  if (g_idx64) return (int)((const long long*)p)[i];
  return ((const int*)p)[i];
}

__device__ __forceinline__ float load_x(const float* X, size_t i) { return X[i]; }
__device__ __forceinline__ float load_x(const __half* X, size_t i) {
  return __half2float(X[i]);
}

// ---------------- init + dtype detect (fused) ----------------
__global__ void init_kernel(const void* __restrict__ ei, int n_nodes, int N) {
  int i = blockIdx.x * blockDim.x + threadIdx.x;
  if (i == 0) {
    const long long* p = (const long long*)ei;
    int ok = 1;
    for (int k = 0; k < 64; k++) {
      long long v = p[k];
      if (v < 0 || v >= (long long)N) { ok = 0; break; }
    }
    g_idx64 = ok;
  }
  if (i < n_nodes) { g_deg[i] = 0; g_fill[i] = 0; }
  if (i < NG * D_HID) g_psum[i] = 0.0f;
  if (i < NG) g_pcnt[i] = 0;
}

// 256-thread exclusive scan of g_deg -> g_rowptr, fused dinv (device body)
__device__ __forceinline__ void scan_body(int n) {
  __shared__ int sums[256];
  int tid   = threadIdx.x;
  int chunk = (n + 255) >> 8;
  int start = tid * chunk;
  int end   = min(start + chunk, n);
  int s = 0;
  for (int i = start; i < end; i++) s += g_deg[i];
  sums[tid] = s;
  __syncthreads();
  for (int off = 1; off < 256; off <<= 1) {
    int v = 0;
    if (tid >= off) v = sums[tid - off];
    __syncthreads();
    sums[tid] += v;
    __syncthreads();
  }
  int run = (tid == 0) ? 0 : sums[tid - 1];
  for (int i = start; i < end; i++) {
    int d = g_deg[i];
    g_rowptr[i] = run;
    g_dinv[i]   = rsqrtf((float)d + 1.0f);   // self-loop: deg+1
    run += d;
  }
  if (end == n && start < n) g_rowptr[n] = run;
  if (n <= start && tid == 0 && n == 0) g_rowptr[0] = 0;
}

// ---------------- GEMM device body: H[M,64] = X[M,K] @ W[K,64] -------------
// BM=128, KB=32, 256 threads, 8x4 register tile. Output stored as fp16.
template <int K, typename T>
__device__ __forceinline__ void gemm_body(const T* __restrict__ X,
                                          const float* __restrict__ W,
                                          __half* __restrict__ H, int M,
                                          int gemmBid, int rowOffset) {
  constexpr int NOUT = D_HID;
  constexpr int BM = 128;
  constexpr int KB = 32;
  constexpr int XS = BM + 4;
  __shared__ __align__(16) float Xs[KB][XS];   // transposed: Xs[k][r]
  __shared__ __align__(16) float Ws[KB][NOUT];

  int tid = threadIdx.x;
  int tx  = tid & 15;
  int ty  = tid >> 4;
  int rb  = rowOffset + gemmBid * BM;

  float acc[8][4];
#pragma unroll
  for (int i = 0; i < 8; i++)
#pragma unroll
    for (int j = 0; j < 4; j++) acc[i][j] = 0.0f;

  for (int k0 = 0; k0 < K; k0 += KB) {
#pragma unroll
    for (int i = tid; i < BM * KB; i += 256) {
      int r = i >> 5, k = i & 31;
      int gr = rb + r;
      Xs[k][r] = (gr < M) ? load_x(X, (size_t)gr * K + k0 + k) : 0.0f;
    }
#pragma unroll
    for (int i = tid; i < KB * NOUT; i += 256) {
      int k = i >> 6, c = i & 63;
      Ws[k][c] = W[(size_t)(k0 + k) * NOUT + c];
    }
    __syncthreads();
#pragma unroll
    for (int k = 0; k < KB; k++) {
      float4 x0 = *reinterpret_cast<const float4*>(&Xs[k][ty * 8]);
      float4 x1 = *reinterpret_cast<const float4*>(&Xs[k][ty * 8 + 4]);
      float4 w  = *reinterpret_cast<const float4*>(&Ws[k][tx * 4]);
      float xr[8] = {x0.x, x0.y, x0.z, x0.w, x1.x, x1.y, x1.z, x1.w};
      float wr[4] = {w.x, w.y, w.z, w.w};
#pragma unroll
      for (int i = 0; i < 8; i++)
#pragma unroll
        for (int j = 0; j < 4; j++) acc[i][j] += xr[i] * wr[j];
    }
    __syncthreads();
  }

#pragma unroll
  for (int i = 0; i < 8; i++) {
    int gr = rb + ty * 8 + i;
    if (gr >= M) continue;
    __half2 h01 = __floats2half2_rn(acc[i][0], acc[i][1]);
    __half2 h23 = __floats2half2_rn(acc[i][2], acc[i][3]);
    uint2 u = make_uint2(*reinterpret_cast<unsigned*>(&h01),
                         *reinterpret_cast<unsigned*>(&h23));
    *reinterpret_cast<uint2*>(H + (size_t)gr * NOUT + tx * 4) = u;
  }
}

// ---- phase 1: GEMM1 blocks + histogram blocks ------------------------------
template <int K, typename T>
__global__ void __launch_bounds__(256, 3)
fused_hist_gemm(const void* __restrict__ ei, int E,
                const T* __restrict__ X, const float* __restrict__ W,
                __half* __restrict__ H, int M, int gemmBlocks, int rowOffset) {
  if ((int)blockIdx.x < gemmBlocks) {
    gemm_body<K>(X, W, H, M, blockIdx.x, rowOffset);
    return;
  }
  int e = (blockIdx.x - gemmBlocks) * blockDim.x + threadIdx.x;
  if (e >= E) return;
  int s = load_idx(ei, e);
  int d = load_idx(ei, (long long)E + e);
  g_src[e] = s;
  g_dst[e] = d;
  atomicAdd(&g_deg[d], 1);
}

// ---- phase 2: scan block (blockIdx 0, scheduled first) + GEMM1 blocks ------
template <int K, typename T>
__global__ void __launch_bounds__(256, 3)
fused_scan_gemm(int N, const T* __restrict__ X, const float* __restrict__ W,
                __half* __restrict__ H, int M, int rowOffset) {
  if (blockIdx.x == 0) {
    scan_body(N);
    return;
  }
  gemm_body<K>(X, W, H, M, blockIdx.x - 1, rowOffset);
}

// ---- phase 3: GEMM1 blocks + CSR-scatter blocks ----------------------------
template <int K, typename T>
__global__ void __launch_bounds__(256, 3)
fused_scatter_gemm(int E, const T* __restrict__ X, const float* __restrict__ W,
                   __half* __restrict__ H, int M, int gemmBlocks, int rowOffset) {
  if ((int)blockIdx.x < gemmBlocks) {
    gemm_body<K>(X, W, H, M, blockIdx.x, rowOffset);
    return;
  }
  int e = (blockIdx.x - gemmBlocks) * blockDim.x + threadIdx.x;
  if (e >= E) return;
  int s = g_src[e];
  int d = g_dst[e];
  int pos = g_rowptr[d] + atomicAdd(&g_fill[d], 1);
  g_edge[pos] = make_int2(s, __float_as_int(g_dinv[s] * g_dinv[d]));
}

// ---- plain GEMM (layer 2) --------------------------------------------------
template <int K, typename T>
__global__ void __launch_bounds__(256, 3)
gemm_kernel(const T* __restrict__ X, const float* __restrict__ W,
            __half* __restrict__ H, int M) {
  gemm_body<K>(X, W, H, M, blockIdx.x, 0);
}

// ------- CSR aggregation core (F=64, warp/node, fp16 gather, MLP=4) --------
__device__ __forceinline__ float2 agg_node(const __half* __restrict__ H,
                                           int n, int lane) {
  float dn = g_dinv[n];
  float ws = dn * dn;
  float2 self = __half22float2(
      __ldg(reinterpret_cast<const __half2*>(H + (size_t)n * D_HID) + lane));
  float a0 = self.x * ws, a1 = self.y * ws;

  int e  = g_rowptr[n];
  int e1 = g_rowptr[n + 1];
  // 4-wide unroll: 4 independent row gathers in flight
  for (; e + 3 < e1; e += 4) {
    int2 v0 = __ldg(&g_edge[e]);
    int2 v1 = __ldg(&g_edge[e + 1]);
    int2 v2 = __ldg(&g_edge[e + 2]);
    int2 v3 = __ldg(&g_edge[e + 3]);
    float2 h0 = __half22float2(
        __ldg(reinterpret_cast<const __half2*>(H + (size_t)v0.x * D_HID) + lane));
    float2 h1 = __half22float2(
        __ldg(reinterpret_cast<const __half2*>(H + (size_t)v1.x * D_HID) + lane));
    float2 h2 = __half22float2(
        __ldg(reinterpret_cast<const __half2*>(H + (size_t)v2.x * D_HID) + lane));
    float2 h3 = __half22float2(
        __ldg(reinterpret_cast<const __half2*>(H + (size_t)v3.x * D_HID) + lane));
    float w0 = __int_as_float(v0.y);
    float w1 = __int_as_float(v1.y);
    float w2 = __int_as_float(v2.y);
    float w3 = __int_as_float(v3.y);
    a0 += w0 * h0.x; a1 += w0 * h0.y;
    a0 += w1 * h1.x; a1 += w1 * h1.y;
    a0 += w2 * h2.x; a1 += w2 * h2.y;
    a0 += w3 * h3.x; a1 += w3 * h3.y;
  }
  for (; e < e1; e++) {
    int2 v = __ldg(&g_edge[e]);
    float2 h = __half22float2(
        __ldg(reinterpret_cast<const __half2*>(H + (size_t)v.x * D_HID) + lane));
    float w = __int_as_float(v.y);
    a0 += w * h.x; a1 += w * h.y;
  }
  return make_float2(a0, a1);
}

__global__ void agg_gelu_kernel(const __half* __restrict__ H,
                                const float* __restrict__ bias,
                                __half* __restrict__ out, int N) {
  int t = blockIdx.x * blockDim.x + threadIdx.x;
  int n = t >> 5, lane = t & 31;
  if (n >= N) return;
  float2 a = agg_node(H, n, lane);
  float2 b = __ldg(reinterpret_cast<const float2*>(bias) + lane);
  float y0 = gelu_fast(a.x + b.x);
  float y1 = gelu_fast(a.y + b.y);
  reinterpret_cast<__half2*>(out + (size_t)n * D_HID)[lane] =
      __floats2half2_rn(y0, y1);
}

// ------- layer-3 agg fused with mean-pool; batch sorted -> smem reduce -----
__global__ void agg_pool_kernel(const __half* __restrict__ H,
                                const void* __restrict__ batch, int N) {
  __shared__ float sacc[D_HID];
  __shared__ int   scnt;
  __shared__ int   sg;
  int tid  = threadIdx.x;
  int lane = tid & 31, wid = tid >> 5;
  int n = blockIdx.x * 8 + wid;

  if (tid == 0) {
    scnt = 0;
    int first = blockIdx.x * 8;
    sg = load_idx(batch, first < N ? first : (N - 1));
  }
  if (tid < D_HID) sacc[tid] = 0.0f;
  __syncthreads();

  if (n < N) {
    float2 a = agg_node(H, n, lane);
    int g = load_idx(batch, n);
    if (g == sg) {
      atomicAdd(&sacc[lane * 2],     a.x);
      atomicAdd(&sacc[lane * 2 + 1], a.y);
      if (lane == 0) atomicAdd(&scnt, 1);
    } else {
      atomicAdd(&g_psum[g * D_HID + lane * 2],     a.x);
      atomicAdd(&g_psum[g * D_HID + lane * 2 + 1], a.y);
      if (lane == 0) atomicAdd(&g_pcnt[g], 1);
    }
  }
  __syncthreads();
  if (scnt > 0) {
    if (tid < D_HID) atomicAdd(&g_psum[sg * D_HID + tid], sacc[tid]);
    if (tid == 0)    atomicAdd(&g_pcnt[sg], scnt);
  }
}

// ------- final tiny GEMM: out[g,:] = mean_g @ W3 + b3 -----------------------
__global__ void final_gemm_kernel(const float* __restrict__ W3,
                                  const float* __restrict__ b3,
                                  float* __restrict__ out) {
  int g = blockIdx.x;
  int j = threadIdx.x;  // 128 threads = D_OUT
  __shared__ float row[D_HID];
  int cnt = g_pcnt[g];
  float inv = (cnt > 0) ? (1.0f / (float)cnt) : 0.0f;
  if (j < D_HID) row[j] = g_psum[g * D_HID + j] * inv;
  __syncthreads();
  float acc = (cnt > 0) ? __ldg(&b3[j]) : 0.0f;
#pragma unroll 8
  for (int k = 0; k < D_HID; k++) acc += row[k] * __ldg(&W3[k * D_OUT + j]);
  out[(size_t)g * D_OUT + j] = acc;
}

// ---------------- launch ----------------
extern "C" void kernel_launch(void* const* d_in, const int* in_sizes, int n_in,
                              void* d_out, int out_size) {
  const float* x     = (const float*)d_in[0];
  const void*  ei    = d_in[1];
  const void*  batch = d_in[2];

  int wi = 3;
  while (wi < n_in && in_sizes[wi] <= 1) wi++;
  const float* W1 = (const float*)d_in[wi + 0];
  const float* b1 = (const float*)d_in[wi + 1];
  const float* W2 = (const float*)d_in[wi + 2];
  const float* b2 = (const float*)d_in[wi + 3];
  const float* W3 = (const float*)d_in[wi + 4];
  const float* b3 = (const float*)d_in[wi + 5];

  int N = in_sizes[2];
  int E = in_sizes[1] / 2;

  __half *bufA, *bufB;
  cudaGetSymbolAddress((void**)&bufA, g_bufA);
  cudaGetSymbolAddress((void**)&bufB, g_bufB);

  const int TB = 256;
  int nb_nodes = (N + TB - 1) / TB;
  int nb_edges = (E + TB - 1) / TB;
  int nb_warp  = (int)(((long long)N * 32 + TB - 1) / TB);
  int nb_gemm  = (N + 127) / 128;

  // Split GEMM1 blocks across the three preprocessing phases (40/20/40).
  int gA = (nb_gemm * 2) / 5;
  int gS = nb_gemm / 5;
  int gB = nb_gemm - gA - gS;
  int rowOffS = gA * 128;
  int rowOffB = (gA + gS) * 128;

  // ---- phase 0: init + dtype detect ----
  init_kernel<<<nb_nodes, TB>>>(ei, N, N);
  // ---- phase 1: GEMM1 || histogram ----
  fused_hist_gemm<D_IN><<<gA + nb_edges, TB>>>(ei, E, x, W1, bufA, N, gA, 0);
  // ---- phase 2: scan (block 0) || GEMM1 ----
  fused_scan_gemm<D_IN><<<1 + gS, TB>>>(N, x, W1, bufA, N, rowOffS);
  // ---- phase 3: GEMM1 || CSR scatter ----
  fused_scatter_gemm<D_IN><<<gB + nb_edges, TB>>>(E, x, W1, bufA, N, gB, rowOffB);

  // ---- layer 1 aggregation + gelu ----
  agg_gelu_kernel<<<nb_warp, TB>>>(bufA, b1, bufB, N);

  // ---- layer 2: GEMM 64->64, agg + gelu ----
  gemm_kernel<D_HID><<<nb_gemm, TB>>>(bufB, W2, bufA, N);
  agg_gelu_kernel<<<nb_warp, TB>>>(bufA, b2, bufB, N);

  // ---- layer 3 (reordered): agg+pool in 64-dim, then [NG,64]@[64,128]+b3 ----
  agg_pool_kernel<<<(N + 7) / 8, TB>>>(bufB, batch, N);
  final_gemm_kernel<<<out_size / D_OUT, D_OUT>>>(W3, b3, (float*)d_out);
}

// round 11
// speedup vs baseline: 1.3874x; 1.0544x over previous
#include <cuda_runtime.h>
#include <cuda_fp16.h>
#include <math.h>
#include <cstdint>
#include <cstddef>

#define NN    50000
#define NE    800000
#define NG    256
#define D_IN  128
#define D_HID 64
#define D_OUT 128

// ---------------- device scratch (no allocations allowed) ----------------
__device__ int   g_deg[NN];
__device__ int   g_fill[NN];
__device__ int   g_rowptr[NN + 1];
__device__ float g_dinv[NN];
__device__ int   g_src[NE];
__device__ int   g_dst[NE];
__device__ __align__(16) int2 g_edge[NE];        // (src, norm-as-int)
__device__ __align__(16) __half g_x16[(size_t)NN * D_IN];
__device__ __align__(16) __half g_Wt1[D_HID * D_IN];   // [n][k] fp16
__device__ __align__(16) __half g_Wt2[D_HID * D_HID];  // [n][k] fp16
__device__ __align__(16) __half g_bufA[(size_t)NN * D_HID];
__device__ __align__(16) __half g_bufB[(size_t)NN * D_HID];
__device__ float g_psum[NG * D_HID];
__device__ int   g_pcnt[NG];
__device__ int   g_idx64;

// ---------------- helpers ----------------
__device__ __forceinline__ float gelu_fast(float x) {
  float s = x + 0.044715f * x * x * x;
  return __fdividef(x, 1.0f + __expf(-1.59576912f * s));
}

__device__ __forceinline__ int load_idx(const void* p, long long i) {
  if (g_idx64) return (int)((const long long*)p)[i];
  return ((const int*)p)[i];
}

// ---------------- init: detect + zero + weight transpose to fp16 ----------
__global__ void init_kernel(const void* __restrict__ ei, int N,
                            const float* __restrict__ W1,
                            const float* __restrict__ W2) {
  int i = blockIdx.x * blockDim.x + threadIdx.x;
  if (i == 0) {
    const long long* p = (const long long*)ei;
    int ok = 1;
    for (int k = 0; k < 64; k++) {
      long long v = p[k];
      if (v < 0 || v >= (long long)N) { ok = 0; break; }
    }
    g_idx64 = ok;
  }
  if (i < N) { g_deg[i] = 0; g_fill[i] = 0; }
  if (i < NG * D_HID) g_psum[i] = 0.0f;
  if (i < NG) g_pcnt[i] = 0;
  // Wt1[n][k] = W1[k][n]   (8192 elems)
  if (i < D_HID * D_IN) {
    int n = i / D_IN, k = i % D_IN;
    g_Wt1[i] = __float2half(W1[(size_t)k * D_HID + n]);
  }
  // Wt2[n][k] = W2[k][n]   (4096 elems)
  if (i < D_HID * D_HID) {
    int n = i / D_HID, k = i % D_HID;
    g_Wt2[i] = __float2half(W2[(size_t)k * D_HID + n]);
  }
}

// ---- K1: x fp32 -> fp16 conversion blocks + histogram blocks --------------
__global__ void fused_convert_hist(const void* __restrict__ ei, int E,
                                   const float* __restrict__ x,
                                   int convBlocks, int convThreads) {
  if ((int)blockIdx.x < convBlocks) {
    int i = blockIdx.x * blockDim.x + threadIdx.x;   // one float4 per thread
    if (i < convThreads) {
      float4 v = __ldg(reinterpret_cast<const float4*>(x) + i);
      __half2 h0 = __floats2half2_rn(v.x, v.y);
      __half2 h1 = __floats2half2_rn(v.z, v.w);
      uint2 u = make_uint2(*reinterpret_cast<unsigned*>(&h0),
                           *reinterpret_cast<unsigned*>(&h1));
      reinterpret_cast<uint2*>(g_x16)[i] = u;
    }
    return;
  }
  int e = (blockIdx.x - convBlocks) * blockDim.x + threadIdx.x;
  if (e >= E) return;
  int s = load_idx(ei, e);
  int d = load_idx(ei, (long long)E + e);
  g_src[e] = s;
  g_dst[e] = d;
  atomicAdd(&g_deg[d], 1);
}

// 256-thread exclusive scan of g_deg -> g_rowptr, fused dinv
__device__ __forceinline__ void scan_body(int n) {
  __shared__ int sums[256];
  int tid   = threadIdx.x;
  int chunk = (n + 255) >> 8;
  int start = tid * chunk;
  int end   = min(start + chunk, n);
  int s = 0;
  for (int i = start; i < end; i++) s += g_deg[i];
  sums[tid] = s;
  __syncthreads();
  for (int off = 1; off < 256; off <<= 1) {
    int v = 0;
    if (tid >= off) v = sums[tid - off];
    __syncthreads();
    sums[tid] += v;
    __syncthreads();
  }
  int run = (tid == 0) ? 0 : sums[tid - 1];
  for (int i = start; i < end; i++) {
    int d = g_deg[i];
    g_rowptr[i] = run;
    g_dinv[i]   = rsqrtf((float)d + 1.0f);   // self-loop: deg+1
    run += d;
  }
  if (end == n && start < n) g_rowptr[n] = run;
}

// ---------------- tensor-core GEMM: H[M,64] = X[M,K] @ Wt^T ----------------
// mma.sync.m16n8k16 fp16xfp16 -> fp32. Warp computes 32 rows x 64 cols.
// Block = 8 warps = 256 rows. All operands straight from global (no smem).
__device__ __forceinline__ void mma16816(float* c, const unsigned* a,
                                         const unsigned* b) {
  asm volatile(
      "mma.sync.aligned.m16n8k16.row.col.f32.f16.f16.f32 "
      "{%0,%1,%2,%3}, {%4,%5,%6,%7}, {%8,%9}, {%0,%1,%2,%3};"
      : "+f"(c[0]), "+f"(c[1]), "+f"(c[2]), "+f"(c[3])
      : "r"(a[0]), "r"(a[1]), "r"(a[2]), "r"(a[3]), "r"(b[0]), "r"(b[1]));
}

template <int K>
__device__ __forceinline__ void gemm_mma_body(const __half* __restrict__ X,
                                              const __half* __restrict__ Wt,
                                              __half* __restrict__ H, int M,
                                              int bid) {
  int warp = threadIdx.x >> 5, lane = threadIdx.x & 31;
  int g = lane >> 2, t = lane & 3;
  int row0 = bid * 256 + warp * 32;

  float acc[2][8][4];
#pragma unroll
  for (int rt = 0; rt < 2; rt++)
#pragma unroll
    for (int j = 0; j < 8; j++)
#pragma unroll
      for (int c = 0; c < 4; c++) acc[rt][j][c] = 0.0f;

#pragma unroll
  for (int k0 = 0; k0 < K; k0 += 16) {
    unsigned a[2][4];
#pragma unroll
    for (int rt = 0; rt < 2; rt++) {
      int ra = row0 + rt * 16 + g;
      int rb = ra + 8;
      if (ra >= M) ra = M - 1;          // clamp: OOB rows discarded at store
      if (rb >= M) rb = M - 1;
      const unsigned* pa =
          reinterpret_cast<const unsigned*>(X + (size_t)ra * K + k0);
      const unsigned* pb =
          reinterpret_cast<const unsigned*>(X + (size_t)rb * K + k0);
      a[rt][0] = pa[t];
      a[rt][1] = pb[t];
      a[rt][2] = pa[t + 4];
      a[rt][3] = pb[t + 4];
    }
#pragma unroll
    for (int j = 0; j < 8; j++) {
      int col = j * 8 + g;
      const unsigned* pw =
          reinterpret_cast<const unsigned*>(Wt + (size_t)col * K + k0);
      unsigned b[2] = {pw[t], pw[t + 4]};
      mma16816(acc[0][j], a[0], b);
      mma16816(acc[1][j], a[1], b);
    }
  }

#pragma unroll
  for (int rt = 0; rt < 2; rt++) {
    int r1 = row0 + rt * 16 + g;
    int r2 = r1 + 8;
#pragma unroll
    for (int j = 0; j < 8; j++) {
      int col = j * 8 + t * 2;
      if (r1 < M) {
        __half2 h = __floats2half2_rn(acc[rt][j][0], acc[rt][j][1]);
        *reinterpret_cast<__half2*>(H + (size_t)r1 * D_HID + col) = h;
      }
      if (r2 < M) {
        __half2 h = __floats2half2_rn(acc[rt][j][2], acc[rt][j][3]);
        *reinterpret_cast<__half2*>(H + (size_t)r2 * D_HID + col) = h;
      }
    }
  }
}

// ---- K2: scan block (blockIdx 0) + all GEMM1 blocks ------------------------
__global__ void __launch_bounds__(256)
fused_scan_gemm1(int N, __half* __restrict__ H, int M) {
  if (blockIdx.x == 0) {
    scan_body(N);
    return;
  }
  gemm_mma_body<D_IN>(g_x16, g_Wt1, H, M, blockIdx.x - 1);
}

// ---- K3: scatter alone, full occupancy -------------------------------------
__global__ void scatter_kernel(int E) {
  int e = blockIdx.x * blockDim.x + threadIdx.x;
  if (e >= E) return;
  int s = g_src[e];
  int d = g_dst[e];
  int pos = g_rowptr[d] + atomicAdd(&g_fill[d], 1);
  g_edge[pos] = make_int2(s, __float_as_int(g_dinv[s] * g_dinv[d]));
}

// ---- GEMM2 (layer 2): bufB fp16 -> bufA fp16 -------------------------------
__global__ void __launch_bounds__(256)
gemm2_kernel(const __half* __restrict__ X, __half* __restrict__ H, int M) {
  gemm_mma_body<D_HID>(X, g_Wt2, H, M, blockIdx.x);
}

// ------- CSR aggregation core (F=64, warp/node, fp16 gather, MLP=4) --------
__device__ __forceinline__ float2 agg_node(const __half* __restrict__ H,
                                           int n, int lane) {
  float dn = g_dinv[n];
  float ws = dn * dn;
  float2 self = __half22float2(
      __ldg(reinterpret_cast<const __half2*>(H + (size_t)n * D_HID) + lane));
  float a0 = self.x * ws, a1 = self.y * ws;

  int e  = g_rowptr[n];
  int e1 = g_rowptr[n + 1];
  for (; e + 3 < e1; e += 4) {
    int2 v0 = __ldg(&g_edge[e]);
    int2 v1 = __ldg(&g_edge[e + 1]);
    int2 v2 = __ldg(&g_edge[e + 2]);
    int2 v3 = __ldg(&g_edge[e + 3]);
    float2 h0 = __half22float2(
        __ldg(reinterpret_cast<const __half2*>(H + (size_t)v0.x * D_HID) + lane));
    float2 h1 = __half22float2(
        __ldg(reinterpret_cast<const __half2*>(H + (size_t)v1.x * D_HID) + lane));
    float2 h2 = __half22float2(
        __ldg(reinterpret_cast<const __half2*>(H + (size_t)v2.x * D_HID) + lane));
    float2 h3 = __half22float2(
        __ldg(reinterpret_cast<const __half2*>(H + (size_t)v3.x * D_HID) + lane));
    float w0 = __int_as_float(v0.y);
    float w1 = __int_as_float(v1.y);
    float w2 = __int_as_float(v2.y);
    float w3 = __int_as_float(v3.y);
    a0 += w0 * h0.x; a1 += w0 * h0.y;
    a0 += w1 * h1.x; a1 += w1 * h1.y;
    a0 += w2 * h2.x; a1 += w2 * h2.y;
    a0 += w3 * h3.x; a1 += w3 * h3.y;
  }
  for (; e < e1; e++) {
    int2 v = __ldg(&g_edge[e]);
    float2 h = __half22float2(
        __ldg(reinterpret_cast<const __half2*>(H + (size_t)v.x * D_HID) + lane));
    float w = __int_as_float(v.y);
    a0 += w * h.x; a1 += w * h.y;
  }
  return make_float2(a0, a1);
}

__global__ void agg_gelu_kernel(const __half* __restrict__ H,
                                const float* __restrict__ bias,
                                __half* __restrict__ out, int N) {
  int t = blockIdx.x * blockDim.x + threadIdx.x;
  int n = t >> 5, lane = t & 31;
  if (n >= N) return;
  float2 a = agg_node(H, n, lane);
  float2 b = __ldg(reinterpret_cast<const float2*>(bias) + lane);
  float y0 = gelu_fast(a.x + b.x);
  float y1 = gelu_fast(a.y + b.y);
  reinterpret_cast<__half2*>(out + (size_t)n * D_HID)[lane] =
      __floats2half2_rn(y0, y1);
}

// ------- layer-3 agg fused with mean-pool; batch sorted -> smem reduce -----
__global__ void agg_pool_kernel(const __half* __restrict__ H,
                                const void* __restrict__ batch, int N) {
  __shared__ float sacc[D_HID];
  __shared__ int   scnt;
  __shared__ int   sg;
  int tid  = threadIdx.x;
  int lane = tid & 31, wid = tid >> 5;
  int n = blockIdx.x * 8 + wid;

  if (tid == 0) {
    scnt = 0;
    int first = blockIdx.x * 8;
    sg = load_idx(batch, first < N ? first : (N - 1));
  }
  if (tid < D_HID) sacc[tid] = 0.0f;
  __syncthreads();

  if (n < N) {
    float2 a = agg_node(H, n, lane);
    int g = load_idx(batch, n);
    if (g == sg) {
      atomicAdd(&sacc[lane * 2],     a.x);
      atomicAdd(&sacc[lane * 2 + 1], a.y);
      if (lane == 0) atomicAdd(&scnt, 1);
    } else {
      atomicAdd(&g_psum[g * D_HID + lane * 2],     a.x);
      atomicAdd(&g_psum[g * D_HID + lane * 2 + 1], a.y);
      if (lane == 0) atomicAdd(&g_pcnt[g], 1);
    }
  }
  __syncthreads();
  if (scnt > 0) {
    if (tid < D_HID) atomicAdd(&g_psum[sg * D_HID + tid], sacc[tid]);
    if (tid == 0)    atomicAdd(&g_pcnt[sg], scnt);
  }
}

// ------- final tiny GEMM: out[g,:] = mean_g @ W3 + b3 -----------------------
__global__ void final_gemm_kernel(const float* __restrict__ W3,
                                  const float* __restrict__ b3,
                                  float* __restrict__ out) {
  int g = blockIdx.x;
  int j = threadIdx.x;  // 128 threads = D_OUT
  __shared__ float row[D_HID];
  int cnt = g_pcnt[g];
  float inv = (cnt > 0) ? (1.0f / (float)cnt) : 0.0f;
  if (j < D_HID) row[j] = g_psum[g * D_HID + j] * inv;
  __syncthreads();
  float acc = (cnt > 0) ? __ldg(&b3[j]) : 0.0f;
#pragma unroll 8
  for (int k = 0; k < D_HID; k++) acc += row[k] * __ldg(&W3[k * D_OUT + j]);
  out[(size_t)g * D_OUT + j] = acc;
}

// ---------------- launch ----------------
extern "C" void kernel_launch(void* const* d_in, const int* in_sizes, int n_in,
                              void* d_out, int out_size) {
  const float* x     = (const float*)d_in[0];
  const void*  ei    = d_in[1];
  const void*  batch = d_in[2];

  int wi = 3;
  while (wi < n_in && in_sizes[wi] <= 1) wi++;
  const float* W1 = (const float*)d_in[wi + 0];
  const float* b1 = (const float*)d_in[wi + 1];
  const float* W2 = (const float*)d_in[wi + 2];
  const float* b2 = (const float*)d_in[wi + 3];
  const float* W3 = (const float*)d_in[wi + 4];
  const float* b3 = (const float*)d_in[wi + 5];

  int N = in_sizes[2];
  int E = in_sizes[1] / 2;

  __half *bufA, *bufB;
  cudaGetSymbolAddress((void**)&bufA, g_bufA);
  cudaGetSymbolAddress((void**)&bufB, g_bufB);

  const int TB = 256;
  int nb_nodes = (N + TB - 1) / TB;
  int nb_edges = (E + TB - 1) / TB;
  int nb_warp  = (int)(((long long)N * 32 + TB - 1) / TB);
  int nb_mma   = (N + 255) / 256;

  int convThreads = (N * D_IN) / 4;                 // one float4 per thread
  int convBlocks  = (convThreads + TB - 1) / TB;

  // K0: init + detect + weight transpose (fp16)
  init_kernel<<<nb_nodes, TB>>>(ei, N, W1, W2);
  // K1: x->fp16 conversion || histogram (both high-occupancy)
  fused_convert_hist<<<convBlocks + nb_edges, TB>>>(ei, E, x, convBlocks,
                                                    convThreads);
  // K2: rowptr scan (block 0) || all of GEMM1 (tensor cores)
  fused_scan_gemm1<<<1 + nb_mma, TB>>>(N, bufA, N);
  // K3: CSR scatter at full occupancy
  scatter_kernel<<<nb_edges, TB>>>(E);

  // layer 1 aggregation + gelu
  agg_gelu_kernel<<<nb_warp, TB>>>(bufA, b1, bufB, N);

  // layer 2: tensor-core GEMM 64->64, agg + gelu
  gemm2_kernel<<<nb_mma, TB>>>(bufB, bufA, N);
  agg_gelu_kernel<<<nb_warp, TB>>>(bufA, b2, bufB, N);

  // layer 3 (reordered): agg+pool in 64-dim, then [NG,64]@[64,128]+b3
  agg_pool_kernel<<<(N + 7) / 8, TB>>>(bufB, batch, N);
  final_gemm_kernel<<<out_size / D_OUT, D_OUT>>>(W3, b3, (float*)d_out);
}